// round 15
// baseline (speedup 1.0000x reference)
#include <cuda_runtime.h>

#define N_USER   200000
#define N_ITEM   100000
#define N_NODES_ 300000
#define EMB      80
#define EMBV     20          // float4 chunks per row
#define FEAT     16
#define NNZ_     1000000
#define BATCH_   4096
#define NSEL     (3 * BATCH_)   // 12288 selected rows
#define NLAYER   3

// ---------------- device scratch ----------------
static __device__ float g_E [(size_t)N_NODES_ * EMB];   // 96 MB
static __device__ float g_LE[(size_t)N_NODES_ * EMB];   // 96 MB
static __device__ float g_LEsel[(size_t)NSEL * EMB];    // 3.9 MB (entry-indexed)
static __device__ float g_Esel [(size_t)NSEL * EMB];    // 3.9 MB (entry-indexed)
static __device__ int   g_nodes[NSEL];
static __device__ int   g_rowptr[N_NODES_ + 1];
static __device__ int   g_cnt[N_NODES_];
static __device__ int   g_bsum[1024];
static __device__ int   g_winner[N_USER];
static __device__ int2  g_edge[NNZ_];                   // packed (col, val-bits)
// frontier sets
static __device__ int   g_flag1[N_NODES_];
static __device__ int   g_flag2[N_NODES_];
static __device__ int   g_list1[N_NODES_];
static __device__ int   g_list2[N_NODES_];
static __device__ int   g_n1;
static __device__ int   g_n2;

// ---------------- CSR build ----------------
__global__ void k_init() {
    int i = blockIdx.x * blockDim.x + threadIdx.x;
    if (i < N_NODES_) {
        g_cnt[i]   = 0;
        g_flag1[i] = 0;
        g_flag2[i] = 0;
    }
    if (i < N_USER) g_winner[i] = -1;
    if (i == 0) { g_n1 = 0; g_n2 = 0; }
}

__global__ void k_hist(const int4* __restrict__ rows4) {
    int i = blockIdx.x * blockDim.x + threadIdx.x;   // NNZ_/4 threads
    if (i < NNZ_ / 4) {
        int4 r = __ldg(&rows4[i]);
        atomicAdd(&g_cnt[r.x], 1);
        atomicAdd(&g_cnt[r.y], 1);
        atomicAdd(&g_cnt[r.z], 1);
        atomicAdd(&g_cnt[r.w], 1);
    }
}

__global__ void k_scan1() {
    __shared__ int s[1024];
    int tid = threadIdx.x;
    int i = blockIdx.x * 1024 + tid;
    int v = (i < N_NODES_) ? g_cnt[i] : 0;
    s[tid] = v; __syncthreads();
    for (int off = 1; off < 1024; off <<= 1) {
        int t = (tid >= off) ? s[tid - off] : 0;
        __syncthreads();
        s[tid] += t;
        __syncthreads();
    }
    if (i < N_NODES_) g_rowptr[i] = s[tid] - v;
    if (tid == 1023) g_bsum[blockIdx.x] = s[1023];
}

__global__ void k_scan2(int nb) {
    __shared__ int s[1024];
    int tid = threadIdx.x;
    int v = (tid < nb) ? g_bsum[tid] : 0;
    s[tid] = v; __syncthreads();
    for (int off = 1; off < 1024; off <<= 1) {
        int t = (tid >= off) ? s[tid - off] : 0;
        __syncthreads();
        s[tid] += t;
        __syncthreads();
    }
    if (tid < nb) g_bsum[tid] = s[tid] - v;
}

__global__ void k_scan3() {
    int i = blockIdx.x * blockDim.x + threadIdx.x;
    if (i < N_NODES_) {
        int excl = g_rowptr[i] + g_bsum[i >> 10];
        g_rowptr[i] = excl;
        g_cnt[i]    = excl;
    }
    if (i == 0) g_rowptr[N_NODES_] = NNZ_;
}

__global__ void k_scatter(const int4* __restrict__ rows4, const int4* __restrict__ cols4,
                          const int4* __restrict__ vals4) {
    int i = blockIdx.x * blockDim.x + threadIdx.x;   // NNZ_/4 threads
    if (i >= NNZ_ / 4) return;
    int4 r = __ldg(&rows4[i]);
    int4 c = __ldg(&cols4[i]);
    int4 v = __ldg(&vals4[i]);
    int p;
    p = atomicAdd(&g_cnt[r.x], 1); g_edge[p] = make_int2(c.x, v.x);
    p = atomicAdd(&g_cnt[r.y], 1); g_edge[p] = make_int2(c.y, v.y);
    p = atomicAdd(&g_cnt[r.z], 1); g_edge[p] = make_int2(c.z, v.z);
    p = atomicAdd(&g_cnt[r.w], 1); g_edge[p] = make_int2(c.w, v.w);
}

// ---------------- E init + blend scatter + node list ----------------
__global__ void k_init_E(const float4* __restrict__ user_tab, const float4* __restrict__ item_tab) {
    int i = blockIdx.x * blockDim.x + threadIdx.x;
    const int tot_u = N_USER * EMBV;
    const int tot   = N_NODES_ * EMBV;
    if (i < tot_u)      ((float4*)g_E)[i] = user_tab[i];
    else if (i < tot)   ((float4*)g_E)[i] = item_tab[i - tot_u];
}

__global__ void k_winner(const int* __restrict__ u_id) {
    int i = blockIdx.x * blockDim.x + threadIdx.x;
    if (i < BATCH_) atomicMax(&g_winner[u_id[i]], i);
}

__global__ void k_blend(const int* __restrict__ u_id, const int* __restrict__ age,
                        const int* __restrict__ sex, const int* __restrict__ month,
                        const int* __restrict__ day, const int* __restrict__ dow,
                        const float* __restrict__ user_tab,
                        const float* __restrict__ age_tab, const float* __restrict__ sex_tab,
                        const float* __restrict__ month_tab, const float* __restrict__ day_tab,
                        const float* __restrict__ dow_tab) {
    int i = blockIdx.x * blockDim.x + threadIdx.x;
    if (i >= BATCH_) return;
    int u = u_id[i];
    if (g_winner[u] != i) return;   // last occurrence wins
    float*       dst = g_E + (size_t)u * EMB;
    const float* src = user_tab + (size_t)u * EMB;
    const float* t0 = age_tab   + age[i]   * FEAT;
    const float* t1 = sex_tab   + sex[i]   * FEAT;
    const float* t2 = month_tab + month[i] * FEAT;
    const float* t3 = day_tab   + day[i]   * FEAT;
    const float* t4 = dow_tab   + dow[i]   * FEAT;
    #pragma unroll
    for (int j = 0; j < FEAT; j++) {
        dst[0*FEAT+j] = 0.5f * (src[0*FEAT+j] + t0[j]);
        dst[1*FEAT+j] = 0.5f * (src[1*FEAT+j] + t1[j]);
        dst[2*FEAT+j] = 0.5f * (src[2*FEAT+j] + t2[j]);
        dst[3*FEAT+j] = 0.5f * (src[3*FEAT+j] + t3[j]);
        dst[4*FEAT+j] = 0.5f * (src[4*FEAT+j] + t4[j]);
    }
}

__global__ void k_nodes(const int* __restrict__ u_id, const int* __restrict__ pos,
                        const int* __restrict__ neg) {
    int i = blockIdx.x * blockDim.x + threadIdx.x;
    if (i >= NSEL) return;
    int node;
    if (i < BATCH_)          node = u_id[i];
    else if (i < 2 * BATCH_) node = N_USER + pos[i - BATCH_];
    else                     node = N_USER + neg[i - 2 * BATCH_];
    g_nodes[i] = node;
}

// ---------------- frontier set construction ----------------
__global__ void k_mark_sel() {
    int w    = (blockIdx.x * blockDim.x + threadIdx.x) >> 5;
    int lane = threadIdx.x & 31;
    if (w >= NSEL) return;
    int row = g_nodes[w];
    if (lane == 0) g_flag1[row] = 1;
    int s = g_rowptr[row], e = g_rowptr[row + 1];
    for (int i = s + lane; i < e; i += 32) g_flag1[g_edge[i].x] = 1;
}

__global__ void k_compact1() {
    int i = blockIdx.x * blockDim.x + threadIdx.x;
    if (i < N_NODES_ && g_flag1[i]) {
        int p = atomicAdd(&g_n1, 1);
        g_list1[p] = i;
    }
}

__global__ void k_mark_list() {
    int n    = g_n1;
    int w0   = (blockIdx.x * blockDim.x + threadIdx.x) >> 5;
    int lane = threadIdx.x & 31;
    int nw   = (gridDim.x * blockDim.x) >> 5;
    for (int idx = w0; idx < n; idx += nw) {
        int row = g_list1[idx];
        if (lane == 0) g_flag2[row] = 1;
        int s = g_rowptr[row], e = g_rowptr[row + 1];
        for (int i = s + lane; i < e; i += 32) g_flag2[g_edge[i].x] = 1;
    }
}

__global__ void k_compact2() {
    int i = blockIdx.x * blockDim.x + threadIdx.x;
    if (i < N_NODES_ && g_flag2[i]) {
        int p = atomicAdd(&g_n2, 1);
        g_list2[p] = i;
    }
}

// ---------------- SpMM over a row list (node-indexed output) ----------------
__global__ void k_spmm_l(int which) {
    int n           = which ? g_n1 : g_n2;
    const int* list = which ? g_list1 : g_list2;
    int gw   = (blockIdx.x * blockDim.x + threadIdx.x) >> 5;
    int lane = threadIdx.x & 31;
    int nw   = (gridDim.x * blockDim.x) >> 5;
    const float4* E4 = (const float4*)g_E;
    float4*       L4 = (float4*)g_LE;
    for (int idx = gw; idx < n; idx += nw) {
        int row = list[idx];
        int s = g_rowptr[row], e = g_rowptr[row + 1];
        if (lane < EMBV) {
            float4 acc = make_float4(0.f, 0.f, 0.f, 0.f);
            for (int i = s; i < e; i++) {
                int2  ev = __ldg(&g_edge[i]);
                float v  = __int_as_float(ev.y);
                float4 x = __ldg(&E4[(size_t)ev.x * EMBV + lane]);
                acc.x = fmaf(v, x.x, acc.x);
                acc.y = fmaf(v, x.y, acc.y);
                acc.z = fmaf(v, x.z, acc.z);
                acc.w = fmaf(v, x.w, acc.w);
            }
            L4[(size_t)row * EMBV + lane] = acc;
        }
    }
}

// Selective SpMM for final layer (entry-indexed output)
__global__ void k_spmm_sel() {
    int gw   = (blockIdx.x * blockDim.x + threadIdx.x) >> 5;
    int lane = threadIdx.x & 31;
    if (gw >= NSEL) return;
    int row = g_nodes[gw];
    const float4* E4 = (const float4*)g_E;
    float4*       L4 = (float4*)g_LEsel;
    int s = g_rowptr[row], e = g_rowptr[row + 1];
    if (lane < EMBV) {
        float4 acc = make_float4(0.f, 0.f, 0.f, 0.f);
        for (int i = s; i < e; i++) {
            int2  ev = __ldg(&g_edge[i]);
            float v  = __int_as_float(ev.y);
            float4 x = __ldg(&E4[(size_t)ev.x * EMBV + lane]);
            acc.x = fmaf(v, x.x, acc.x);
            acc.y = fmaf(v, x.y, acc.y);
            acc.z = fmaf(v, x.z, acc.z);
            acc.w = fmaf(v, x.w, acc.w);
        }
        L4[(size_t)gw * EMBV + lane] = acc;
    }
}

// ---------------- GEMM + bias + leaky (proven scalar core) ----------------
#define GBM 64
#define GT  160
#define XS  164   // padded row stride (floats)

__device__ __forceinline__ void fma4(float4& a, float s, const float4 w) {
    a.x = fmaf(s, w.x, a.x);
    a.y = fmaf(s, w.y, a.y);
    a.z = fmaf(s, w.z, a.z);
    a.w = fmaf(s, w.w, a.w);
}

__device__ __forceinline__ void gemm_core_epilogue(
        const float* Xs, const float* Bs, int tid,
        const float* __restrict__ W1l, const float* __restrict__ W2l,
        float4* __restrict__ out4, const int* __restrict__ list,
        int row0, int row_limit) {
    int tx = tid % EMBV;
    int ty = tid / EMBV;

    float4 acc[8];
    #pragma unroll
    for (int r = 0; r < 8; r++) acc[r] = make_float4(0.f, 0.f, 0.f, 0.f);

    const float4* W14 = (const float4*)W1l;
    const float4* W24 = (const float4*)W2l;
    const float*  xb  = Xs + (ty * 8) * XS;

    for (int k = 0; k < EMB; k += 4) {
        float4 w0 = __ldg(&W14[(k + 0) * EMBV + tx]);
        float4 w1 = __ldg(&W14[(k + 1) * EMBV + tx]);
        float4 w2 = __ldg(&W14[(k + 2) * EMBV + tx]);
        float4 w3 = __ldg(&W14[(k + 3) * EMBV + tx]);
        #pragma unroll
        for (int r = 0; r < 8; r++) {
            float4 xv = *(const float4*)(xb + r * XS + k);
            fma4(acc[r], xv.x, w0);
            fma4(acc[r], xv.y, w1);
            fma4(acc[r], xv.z, w2);
            fma4(acc[r], xv.w, w3);
        }
    }
    for (int k = 0; k < EMB; k += 4) {
        float4 w0 = __ldg(&W24[(k + 0) * EMBV + tx]);
        float4 w1 = __ldg(&W24[(k + 1) * EMBV + tx]);
        float4 w2 = __ldg(&W24[(k + 2) * EMBV + tx]);
        float4 w3 = __ldg(&W24[(k + 3) * EMBV + tx]);
        #pragma unroll
        for (int r = 0; r < 8; r++) {
            float4 xv = *(const float4*)(xb + r * XS + EMB + k);
            fma4(acc[r], xv.x, w0);
            fma4(acc[r], xv.y, w1);
            fma4(acc[r], xv.z, w2);
            fma4(acc[r], xv.w, w3);
        }
    }

    float4 b = ((const float4*)Bs)[tx];
    #pragma unroll
    for (int r = 0; r < 8; r++) {
        int gr = row0 + ty * 8 + r;
        if (gr < row_limit) {
            float4 v;
            v.x = acc[r].x + b.x;
            v.y = acc[r].y + b.y;
            v.z = acc[r].z + b.z;
            v.w = acc[r].w + b.w;
            v.x = (v.x > 0.f) ? v.x : 0.2f * v.x;
            v.y = (v.y > 0.f) ? v.y : 0.2f * v.y;
            v.z = (v.z > 0.f) ? v.z : 0.2f * v.z;
            v.w = (v.w > 0.f) ? v.w : 0.2f * v.w;
            int orow = list ? list[gr] : gr;
            out4[(size_t)orow * EMBV + tx] = v;
        }
    }
}

__global__ __launch_bounds__(GT) void k_gemm_l(int which,
                                               const float* __restrict__ W1l,
                                               const float* __restrict__ b1l,
                                               const float* __restrict__ W2l,
                                               const float* __restrict__ b2l) {
    __shared__ float Xs[GBM * XS];
    __shared__ float Bs[EMB];

    int n           = which ? g_n1 : g_n2;
    const int* list = which ? g_list1 : g_list2;
    int tid  = threadIdx.x;
    int row0 = blockIdx.x * GBM;
    if (row0 >= n) return;

    if (tid < EMB) Bs[tid] = 2.0f * b1l[tid] + b2l[tid];

    const float4* E4 = (const float4*)g_E;
    const float4* L4 = (const float4*)g_LE;
    for (int j = tid; j < GBM * EMBV; j += GT) {
        int r = j / EMBV, c = j % EMBV;
        int idx = row0 + r;
        float4 le = make_float4(0.f, 0.f, 0.f, 0.f), e = le;
        if (idx < n) {
            int node = list[idx];
            le = L4[(size_t)node * EMBV + c];
            e  = E4[(size_t)node * EMBV + c];
        }
        float4* xr = (float4*)(Xs + r * XS);
        xr[c]        = make_float4(le.x + e.x, le.y + e.y, le.z + e.z, le.w + e.w);
        xr[EMBV + c] = make_float4(le.x * e.x, le.y * e.y, le.z * e.z, le.w * e.w);
    }
    __syncthreads();

    gemm_core_epilogue(Xs, Bs, tid, W1l, W2l, (float4*)g_E, list, row0, n);
}

__global__ __launch_bounds__(GT) void k_gemm_sel(const float* __restrict__ W1l,
                                                 const float* __restrict__ b1l,
                                                 const float* __restrict__ W2l,
                                                 const float* __restrict__ b2l) {
    __shared__ float Xs[GBM * XS];
    __shared__ float Bs[EMB];

    int tid  = threadIdx.x;
    int row0 = blockIdx.x * GBM;

    if (tid < EMB) Bs[tid] = 2.0f * b1l[tid] + b2l[tid];

    const float4* E4 = (const float4*)g_E;
    const float4* L4 = (const float4*)g_LEsel;
    for (int j = tid; j < GBM * EMBV; j += GT) {
        int r = j / EMBV, c = j % EMBV;
        int entry = row0 + r;
        int node  = g_nodes[entry];
        float4 le = L4[(size_t)entry * EMBV + c];
        float4 e  = E4[(size_t)node  * EMBV + c];
        float4* xr = (float4*)(Xs + r * XS);
        xr[c]        = make_float4(le.x + e.x, le.y + e.y, le.z + e.z, le.w + e.w);
        xr[EMBV + c] = make_float4(le.x * e.x, le.y * e.y, le.z * e.z, le.w * e.w);
    }
    __syncthreads();

    gemm_core_epilogue(Xs, Bs, tid, W1l, W2l, (float4*)g_Esel, nullptr, row0, NSEL);
}

// ---------------- gather + row-normalize selected rows into output ----------------
__global__ void k_gather(const int* __restrict__ u_id, const int* __restrict__ pos,
                         const int* __restrict__ neg, float* __restrict__ out, int layer) {
    int gw   = (blockIdx.x * blockDim.x + threadIdx.x) >> 5;
    int lane = threadIdx.x & 31;
    if (gw >= NSEL) return;
    int node;
    if (gw < BATCH_)          node = u_id[gw];
    else if (gw < 2 * BATCH_) node = N_USER + pos[gw - BATCH_];
    else                      node = N_USER + neg[gw - 2 * BATCH_];

    const float4* E4 = (const float4*)g_E;
    float4 v = make_float4(0.f, 0.f, 0.f, 0.f);
    if (lane < EMBV) v = E4[(size_t)node * EMBV + lane];
    float ss = v.x * v.x + v.y * v.y + v.z * v.z + v.w * v.w;
    #pragma unroll
    for (int o = 16; o; o >>= 1) ss += __shfl_xor_sync(0xffffffffu, ss, o);
    float scale = 1.0f;
    if (layer > 0) scale = 1.0f / fmaxf(sqrtf(ss), 1e-12f);
    if (lane < EMBV) {
        float4 r = make_float4(v.x * scale, v.y * scale, v.z * scale, v.w * scale);
        ((float4*)(out + (size_t)gw * (4 * EMB) + layer * EMB))[lane] = r;
    }
}

__global__ void k_gather_sel(float* __restrict__ out, int layer) {
    int gw   = (blockIdx.x * blockDim.x + threadIdx.x) >> 5;
    int lane = threadIdx.x & 31;
    if (gw >= NSEL) return;
    const float4* E4 = (const float4*)g_Esel;
    float4 v = make_float4(0.f, 0.f, 0.f, 0.f);
    if (lane < EMBV) v = E4[(size_t)gw * EMBV + lane];
    float ss = v.x * v.x + v.y * v.y + v.z * v.z + v.w * v.w;
    #pragma unroll
    for (int o = 16; o; o >>= 1) ss += __shfl_xor_sync(0xffffffffu, ss, o);
    float scale = 1.0f / fmaxf(sqrtf(ss), 1e-12f);
    if (lane < EMBV) {
        float4 r = make_float4(v.x * scale, v.y * scale, v.z * scale, v.w * scale);
        ((float4*)(out + (size_t)gw * (4 * EMB) + layer * EMB))[lane] = r;
    }
}

// ---------------- launch ----------------
extern "C" void kernel_launch(void* const* d_in, const int* in_sizes, int n_in,
                              void* d_out, int out_size) {
    const int*   u_id      = (const int*)d_in[0];
    const int*   age       = (const int*)d_in[1];
    const int*   sex       = (const int*)d_in[2];
    const int*   month     = (const int*)d_in[3];
    const int*   day       = (const int*)d_in[4];
    const int*   dow       = (const int*)d_in[5];
    const int*   pos       = (const int*)d_in[6];
    const int*   neg       = (const int*)d_in[7];
    const int*   lrows     = (const int*)d_in[8];
    const int*   lcols     = (const int*)d_in[9];
    const float* lvals     = (const float*)d_in[10];
    const float* user_tab  = (const float*)d_in[11];
    const float* item_tab  = (const float*)d_in[12];
    const float* age_tab   = (const float*)d_in[13];
    const float* sex_tab   = (const float*)d_in[14];
    const float* month_tab = (const float*)d_in[15];
    const float* day_tab   = (const float*)d_in[16];
    const float* dow_tab   = (const float*)d_in[17];
    const float* W1        = (const float*)d_in[18];
    const float* b1        = (const float*)d_in[19];
    const float* W2        = (const float*)d_in[20];
    const float* b2        = (const float*)d_in[21];
    float* out = (float*)d_out;

    const int GMAX = (N_NODES_ + GBM - 1) / GBM;

    // Side stream + events for capture fork-join (created per call; leaked —
    // destroying during active capture would invalidate it; only ~2-3 calls total).
    cudaStream_t sB;
    cudaStreamCreateWithFlags(&sB, cudaStreamNonBlocking);
    cudaEvent_t eFork, eNodes, eG0, eF1, eG1, eF2, eG2;
    cudaEventCreateWithFlags(&eFork,  cudaEventDisableTiming);
    cudaEventCreateWithFlags(&eNodes, cudaEventDisableTiming);
    cudaEventCreateWithFlags(&eG0,    cudaEventDisableTiming);
    cudaEventCreateWithFlags(&eF1,    cudaEventDisableTiming);
    cudaEventCreateWithFlags(&eG1,    cudaEventDisableTiming);
    cudaEventCreateWithFlags(&eF2,    cudaEventDisableTiming);
    cudaEventCreateWithFlags(&eG2,    cudaEventDisableTiming);

    // ---- fork: sB = E-init chain, main = CSR chain ----
    cudaEventRecord(eFork, 0);
    cudaStreamWaitEvent(sB, eFork, 0);

    // main: CSR build
    k_init<<<(N_NODES_ + 255) / 256, 256>>>();
    k_hist<<<(NNZ_ / 4 + 255) / 256, 256>>>((const int4*)lrows);
    int nb = (N_NODES_ + 1023) / 1024;
    k_scan1<<<nb, 1024>>>();
    k_scan2<<<1, 1024>>>(nb);
    k_scan3<<<(N_NODES_ + 255) / 256, 256>>>();
    k_scatter<<<(NNZ_ / 4 + 255) / 256, 256>>>((const int4*)lrows, (const int4*)lcols,
                                               (const int4*)lvals);

    // sB: E0 + blend + node list + layer-0 gather (independent of CSR)
    k_init_E<<<(N_NODES_ * EMBV + 255) / 256, 256, 0, sB>>>((const float4*)user_tab,
                                                            (const float4*)item_tab);
    k_winner<<<(BATCH_ + 255) / 256, 256, 0, sB>>>(u_id);
    k_blend<<<(BATCH_ + 255) / 256, 256, 0, sB>>>(u_id, age, sex, month, day, dow, user_tab,
                                                  age_tab, sex_tab, month_tab, day_tab, dow_tab);
    k_nodes<<<(NSEL + 255) / 256, 256, 0, sB>>>(u_id, pos, neg);
    cudaEventRecord(eNodes, sB);
    k_gather<<<(NSEL * 32 + 255) / 256, 256, 0, sB>>>(u_id, pos, neg, out, 0);
    cudaEventRecord(eG0, sB);

    // main: frontier sets (needs CSR + nodes)
    cudaStreamWaitEvent(0, eNodes, 0);
    k_mark_sel<<<(NSEL * 32 + 255) / 256, 256>>>();
    k_compact1<<<(N_NODES_ + 255) / 256, 256>>>();
    k_mark_list<<<1024, 256>>>();
    k_compact2<<<(N_NODES_ + 255) / 256, 256>>>();

    // layer 0: spmm reads g_E (after blend, ordered via eNodes wait above);
    // gemm writes g_E rows S2 ⊇ Ssel — must wait for gather0 (reads E0).
    k_spmm_l<<<2048, 256>>>(0);
    cudaStreamWaitEvent(0, eG0, 0);
    k_gemm_l<<<GMAX, GT>>>(0, W1, b1, W2, b2);

    // gather(1) on sB overlapped with spmm(1); gemm(1) waits for it.
    cudaEventRecord(eF1, 0);
    cudaStreamWaitEvent(sB, eF1, 0);
    k_gather<<<(NSEL * 32 + 255) / 256, 256, 0, sB>>>(u_id, pos, neg, out, 1);
    cudaEventRecord(eG1, sB);

    k_spmm_l<<<2048, 256>>>(1);
    cudaStreamWaitEvent(0, eG1, 0);
    k_gemm_l<<<GMAX, GT>>>(1, W1 + (size_t)EMB * EMB, b1 + EMB,
                              W2 + (size_t)EMB * EMB, b2 + EMB);

    // gather(2) on sB overlapped with spmm_sel (both read-only on g_E).
    cudaEventRecord(eF2, 0);
    cudaStreamWaitEvent(sB, eF2, 0);
    k_gather<<<(NSEL * 32 + 255) / 256, 256, 0, sB>>>(u_id, pos, neg, out, 2);
    cudaEventRecord(eG2, sB);

    k_spmm_sel<<<(NSEL * 32 + 255) / 256, 256>>>();
    cudaStreamWaitEvent(0, eG2, 0);   // joins sB back into main (required for capture)
    k_gemm_sel<<<NSEL / GBM, GT>>>(W1 + (size_t)2 * EMB * EMB, b1 + 2 * EMB,
                                   W2 + (size_t)2 * EMB * EMB, b2 + 2 * EMB);
    k_gather_sel<<<(NSEL * 32 + 255) / 256, 256>>>(out, NLAYER);
}

// round 16
// speedup vs baseline: 1.0041x; 1.0041x over previous
#include <cuda_runtime.h>

#define N_USER   200000
#define N_ITEM   100000
#define N_NODES_ 300000
#define EMB      80
#define EMBV     20          // float4 chunks per row
#define FEAT     16
#define NNZ_     1000000
#define BATCH_   4096
#define NSEL     (3 * BATCH_)   // 12288 selected rows
#define NLAYER   3

typedef unsigned long long ull;

// ---------------- device scratch ----------------
static __device__ float g_E [(size_t)N_NODES_ * EMB];   // 96 MB (E1/E2; E0 blended rows)
static __device__ float g_LE[(size_t)N_NODES_ * EMB];   // 96 MB
static __device__ float g_LEsel[(size_t)NSEL * EMB];    // entry-indexed
static __device__ float g_Esel [(size_t)NSEL * EMB];    // entry-indexed
static __device__ ull   g_ptr[N_NODES_];                // virtual E0 row pointers
static __device__ int   g_nodes[NSEL];
static __device__ int   g_rowptr[N_NODES_ + 1];
static __device__ int   g_cnt[N_NODES_];
static __device__ int   g_bsum[1024];
static __device__ int   g_winner[N_USER];
static __device__ int2  g_edge[NNZ_];                   // packed (col, val-bits)
// frontier sets
static __device__ int   g_flag1[N_NODES_];
static __device__ int   g_flag2[N_NODES_];
static __device__ int   g_list1[N_NODES_];
static __device__ int   g_list2[N_NODES_];
static __device__ int   g_n1;
static __device__ int   g_n2;

// ---------------- CSR build ----------------
__global__ void k_init() {
    int i = blockIdx.x * blockDim.x + threadIdx.x;
    if (i < N_NODES_) {
        g_cnt[i]   = 0;
        g_flag1[i] = 0;
        g_flag2[i] = 0;
    }
    if (i < N_USER) g_winner[i] = -1;
    if (i == 0) { g_n1 = 0; g_n2 = 0; }
}

__global__ void k_init_ptr(const float* __restrict__ user_tab,
                           const float* __restrict__ item_tab) {
    int i = blockIdx.x * blockDim.x + threadIdx.x;
    if (i < N_NODES_) {
        const float* p = (i < N_USER) ? (user_tab + (size_t)i * EMB)
                                      : (item_tab + (size_t)(i - N_USER) * EMB);
        g_ptr[i] = (ull)p;
    }
}

__global__ void k_hist(const int4* __restrict__ rows4) {
    int i = blockIdx.x * blockDim.x + threadIdx.x;
    if (i < NNZ_ / 4) {
        int4 r = __ldg(&rows4[i]);
        atomicAdd(&g_cnt[r.x], 1);
        atomicAdd(&g_cnt[r.y], 1);
        atomicAdd(&g_cnt[r.z], 1);
        atomicAdd(&g_cnt[r.w], 1);
    }
}

__global__ void k_scan1() {
    __shared__ int s[1024];
    int tid = threadIdx.x;
    int i = blockIdx.x * 1024 + tid;
    int v = (i < N_NODES_) ? g_cnt[i] : 0;
    s[tid] = v; __syncthreads();
    for (int off = 1; off < 1024; off <<= 1) {
        int t = (tid >= off) ? s[tid - off] : 0;
        __syncthreads();
        s[tid] += t;
        __syncthreads();
    }
    if (i < N_NODES_) g_rowptr[i] = s[tid] - v;
    if (tid == 1023) g_bsum[blockIdx.x] = s[1023];
}

__global__ void k_scan2(int nb) {
    __shared__ int s[1024];
    int tid = threadIdx.x;
    int v = (tid < nb) ? g_bsum[tid] : 0;
    s[tid] = v; __syncthreads();
    for (int off = 1; off < 1024; off <<= 1) {
        int t = (tid >= off) ? s[tid - off] : 0;
        __syncthreads();
        s[tid] += t;
        __syncthreads();
    }
    if (tid < nb) g_bsum[tid] = s[tid] - v;
}

__global__ void k_scan3() {
    int i = blockIdx.x * blockDim.x + threadIdx.x;
    if (i < N_NODES_) {
        int excl = g_rowptr[i] + g_bsum[i >> 10];
        g_rowptr[i] = excl;
        g_cnt[i]    = excl;
    }
    if (i == 0) g_rowptr[N_NODES_] = NNZ_;
}

__global__ void k_scatter(const int4* __restrict__ rows4, const int4* __restrict__ cols4,
                          const int4* __restrict__ vals4) {
    int i = blockIdx.x * blockDim.x + threadIdx.x;
    if (i >= NNZ_ / 4) return;
    int4 r = __ldg(&rows4[i]);
    int4 c = __ldg(&cols4[i]);
    int4 v = __ldg(&vals4[i]);
    int p;
    p = atomicAdd(&g_cnt[r.x], 1); g_edge[p] = make_int2(c.x, v.x);
    p = atomicAdd(&g_cnt[r.y], 1); g_edge[p] = make_int2(c.y, v.y);
    p = atomicAdd(&g_cnt[r.z], 1); g_edge[p] = make_int2(c.z, v.z);
    p = atomicAdd(&g_cnt[r.w], 1); g_edge[p] = make_int2(c.w, v.w);
}

// ---------------- blend scatter (writes into g_E, repoints g_ptr) ----------------
__global__ void k_winner(const int* __restrict__ u_id) {
    int i = blockIdx.x * blockDim.x + threadIdx.x;
    if (i < BATCH_) atomicMax(&g_winner[u_id[i]], i);
}

__global__ void k_blend(const int* __restrict__ u_id, const int* __restrict__ age,
                        const int* __restrict__ sex, const int* __restrict__ month,
                        const int* __restrict__ day, const int* __restrict__ dow,
                        const float* __restrict__ user_tab,
                        const float* __restrict__ age_tab, const float* __restrict__ sex_tab,
                        const float* __restrict__ month_tab, const float* __restrict__ day_tab,
                        const float* __restrict__ dow_tab) {
    int i = blockIdx.x * blockDim.x + threadIdx.x;
    if (i >= BATCH_) return;
    int u = u_id[i];
    if (g_winner[u] != i) return;   // last occurrence wins
    float*       dst = g_E + (size_t)u * EMB;
    const float* src = user_tab + (size_t)u * EMB;
    const float* t0 = age_tab   + age[i]   * FEAT;
    const float* t1 = sex_tab   + sex[i]   * FEAT;
    const float* t2 = month_tab + month[i] * FEAT;
    const float* t3 = day_tab   + day[i]   * FEAT;
    const float* t4 = dow_tab   + dow[i]   * FEAT;
    #pragma unroll
    for (int j = 0; j < FEAT; j++) {
        dst[0*FEAT+j] = 0.5f * (src[0*FEAT+j] + t0[j]);
        dst[1*FEAT+j] = 0.5f * (src[1*FEAT+j] + t1[j]);
        dst[2*FEAT+j] = 0.5f * (src[2*FEAT+j] + t2[j]);
        dst[3*FEAT+j] = 0.5f * (src[3*FEAT+j] + t3[j]);
        dst[4*FEAT+j] = 0.5f * (src[4*FEAT+j] + t4[j]);
    }
    g_ptr[u] = (ull)dst;   // repoint virtual E0 row
}

__global__ void k_nodes(const int* __restrict__ u_id, const int* __restrict__ pos,
                        const int* __restrict__ neg) {
    int i = blockIdx.x * blockDim.x + threadIdx.x;
    if (i >= NSEL) return;
    int node;
    if (i < BATCH_)          node = u_id[i];
    else if (i < 2 * BATCH_) node = N_USER + pos[i - BATCH_];
    else                     node = N_USER + neg[i - 2 * BATCH_];
    g_nodes[i] = node;
}

// ---------------- frontier set construction ----------------
__global__ void k_mark_sel() {
    int w    = (blockIdx.x * blockDim.x + threadIdx.x) >> 5;
    int lane = threadIdx.x & 31;
    if (w >= NSEL) return;
    int row = g_nodes[w];
    if (lane == 0) g_flag1[row] = 1;
    int s = g_rowptr[row], e = g_rowptr[row + 1];
    for (int i = s + lane; i < e; i += 32) g_flag1[g_edge[i].x] = 1;
}

__global__ void k_compact1() {
    int i = blockIdx.x * blockDim.x + threadIdx.x;
    if (i < N_NODES_ && g_flag1[i]) {
        int p = atomicAdd(&g_n1, 1);
        g_list1[p] = i;
    }
}

__global__ void k_mark_list() {
    int n    = g_n1;
    int w0   = (blockIdx.x * blockDim.x + threadIdx.x) >> 5;
    int lane = threadIdx.x & 31;
    int nw   = (gridDim.x * blockDim.x) >> 5;
    for (int idx = w0; idx < n; idx += nw) {
        int row = g_list1[idx];
        if (lane == 0) g_flag2[row] = 1;
        int s = g_rowptr[row], e = g_rowptr[row + 1];
        for (int i = s + lane; i < e; i += 32) g_flag2[g_edge[i].x] = 1;
    }
}

__global__ void k_compact2() {
    int i = blockIdx.x * blockDim.x + threadIdx.x;
    if (i < N_NODES_ && g_flag2[i]) {
        int p = atomicAdd(&g_n2, 1);
        g_list2[p] = i;
    }
}

// ---------------- SpMM over a row list (node-indexed output) ----------------
// virt != 0: read E0 through g_ptr; else read g_E directly.
__global__ void k_spmm_l(int which, int virt) {
    int n           = which ? g_n1 : g_n2;
    const int* list = which ? g_list1 : g_list2;
    int gw   = (blockIdx.x * blockDim.x + threadIdx.x) >> 5;
    int lane = threadIdx.x & 31;
    int nw   = (gridDim.x * blockDim.x) >> 5;
    const float4* E4 = (const float4*)g_E;
    float4*       L4 = (float4*)g_LE;
    for (int idx = gw; idx < n; idx += nw) {
        int row = list[idx];
        int s = g_rowptr[row], e = g_rowptr[row + 1];
        if (lane < EMBV) {
            float4 acc = make_float4(0.f, 0.f, 0.f, 0.f);
            for (int i = s; i < e; i++) {
                int2  ev = __ldg(&g_edge[i]);
                float v  = __int_as_float(ev.y);
                const float4* src = virt ? (const float4*)g_ptr[ev.x]
                                         : &E4[(size_t)ev.x * EMBV];
                float4 x = __ldg(&src[lane]);
                acc.x = fmaf(v, x.x, acc.x);
                acc.y = fmaf(v, x.y, acc.y);
                acc.z = fmaf(v, x.z, acc.z);
                acc.w = fmaf(v, x.w, acc.w);
            }
            L4[(size_t)row * EMBV + lane] = acc;
        }
    }
}

// Selective SpMM for final layer (reads E2 from g_E; entry-indexed output)
__global__ void k_spmm_sel() {
    int gw   = (blockIdx.x * blockDim.x + threadIdx.x) >> 5;
    int lane = threadIdx.x & 31;
    if (gw >= NSEL) return;
    int row = g_nodes[gw];
    const float4* E4 = (const float4*)g_E;
    float4*       L4 = (float4*)g_LEsel;
    int s = g_rowptr[row], e = g_rowptr[row + 1];
    if (lane < EMBV) {
        float4 acc = make_float4(0.f, 0.f, 0.f, 0.f);
        for (int i = s; i < e; i++) {
            int2  ev = __ldg(&g_edge[i]);
            float v  = __int_as_float(ev.y);
            float4 x = __ldg(&E4[(size_t)ev.x * EMBV + lane]);
            acc.x = fmaf(v, x.x, acc.x);
            acc.y = fmaf(v, x.y, acc.y);
            acc.z = fmaf(v, x.z, acc.z);
            acc.w = fmaf(v, x.w, acc.w);
        }
        L4[(size_t)gw * EMBV + lane] = acc;
    }
}

// ---------------- GEMM + bias + leaky (proven scalar core) ----------------
#define GBM 64
#define GT  160
#define XS  164   // padded row stride (floats)

__device__ __forceinline__ void fma4(float4& a, float s, const float4 w) {
    a.x = fmaf(s, w.x, a.x);
    a.y = fmaf(s, w.y, a.y);
    a.z = fmaf(s, w.z, a.z);
    a.w = fmaf(s, w.w, a.w);
}

__device__ __forceinline__ void gemm_core_epilogue(
        const float* Xs, const float* Bs, int tid,
        const float* __restrict__ W1l, const float* __restrict__ W2l,
        float4* __restrict__ out4, const int* __restrict__ list,
        int row0, int row_limit) {
    int tx = tid % EMBV;
    int ty = tid / EMBV;

    float4 acc[8];
    #pragma unroll
    for (int r = 0; r < 8; r++) acc[r] = make_float4(0.f, 0.f, 0.f, 0.f);

    const float4* W14 = (const float4*)W1l;
    const float4* W24 = (const float4*)W2l;
    const float*  xb  = Xs + (ty * 8) * XS;

    for (int k = 0; k < EMB; k += 4) {
        float4 w0 = __ldg(&W14[(k + 0) * EMBV + tx]);
        float4 w1 = __ldg(&W14[(k + 1) * EMBV + tx]);
        float4 w2 = __ldg(&W14[(k + 2) * EMBV + tx]);
        float4 w3 = __ldg(&W14[(k + 3) * EMBV + tx]);
        #pragma unroll
        for (int r = 0; r < 8; r++) {
            float4 xv = *(const float4*)(xb + r * XS + k);
            fma4(acc[r], xv.x, w0);
            fma4(acc[r], xv.y, w1);
            fma4(acc[r], xv.z, w2);
            fma4(acc[r], xv.w, w3);
        }
    }
    for (int k = 0; k < EMB; k += 4) {
        float4 w0 = __ldg(&W24[(k + 0) * EMBV + tx]);
        float4 w1 = __ldg(&W24[(k + 1) * EMBV + tx]);
        float4 w2 = __ldg(&W24[(k + 2) * EMBV + tx]);
        float4 w3 = __ldg(&W24[(k + 3) * EMBV + tx]);
        #pragma unroll
        for (int r = 0; r < 8; r++) {
            float4 xv = *(const float4*)(xb + r * XS + EMB + k);
            fma4(acc[r], xv.x, w0);
            fma4(acc[r], xv.y, w1);
            fma4(acc[r], xv.z, w2);
            fma4(acc[r], xv.w, w3);
        }
    }

    float4 b = ((const float4*)Bs)[tx];
    #pragma unroll
    for (int r = 0; r < 8; r++) {
        int gr = row0 + ty * 8 + r;
        if (gr < row_limit) {
            float4 v;
            v.x = acc[r].x + b.x;
            v.y = acc[r].y + b.y;
            v.z = acc[r].z + b.z;
            v.w = acc[r].w + b.w;
            v.x = (v.x > 0.f) ? v.x : 0.2f * v.x;
            v.y = (v.y > 0.f) ? v.y : 0.2f * v.y;
            v.z = (v.z > 0.f) ? v.z : 0.2f * v.z;
            v.w = (v.w > 0.f) ? v.w : 0.2f * v.w;
            int orow = list ? list[gr] : gr;
            out4[(size_t)orow * EMBV + tx] = v;
        }
    }
}

// List-driven GEMM; virt != 0 stages E via g_ptr (layer 0 only).
__global__ __launch_bounds__(GT) void k_gemm_l(int which, int virt,
                                               const float* __restrict__ W1l,
                                               const float* __restrict__ b1l,
                                               const float* __restrict__ W2l,
                                               const float* __restrict__ b2l) {
    __shared__ float Xs[GBM * XS];
    __shared__ float Bs[EMB];

    int n           = which ? g_n1 : g_n2;
    const int* list = which ? g_list1 : g_list2;
    int tid  = threadIdx.x;
    int row0 = blockIdx.x * GBM;
    if (row0 >= n) return;

    if (tid < EMB) Bs[tid] = 2.0f * b1l[tid] + b2l[tid];

    const float4* E4 = (const float4*)g_E;
    const float4* L4 = (const float4*)g_LE;
    for (int j = tid; j < GBM * EMBV; j += GT) {
        int r = j / EMBV, c = j % EMBV;
        int idx = row0 + r;
        float4 le = make_float4(0.f, 0.f, 0.f, 0.f), e = le;
        if (idx < n) {
            int node = list[idx];
            le = L4[(size_t)node * EMBV + c];
            const float4* ep = virt ? (const float4*)g_ptr[node]
                                    : &E4[(size_t)node * EMBV];
            e = __ldg(&ep[c]);
        }
        float4* xr = (float4*)(Xs + r * XS);
        xr[c]        = make_float4(le.x + e.x, le.y + e.y, le.z + e.z, le.w + e.w);
        xr[EMBV + c] = make_float4(le.x * e.x, le.y * e.y, le.z * e.z, le.w * e.w);
    }
    __syncthreads();

    gemm_core_epilogue(Xs, Bs, tid, W1l, W2l, (float4*)g_E, list, row0, n);
}

__global__ __launch_bounds__(GT) void k_gemm_sel(const float* __restrict__ W1l,
                                                 const float* __restrict__ b1l,
                                                 const float* __restrict__ W2l,
                                                 const float* __restrict__ b2l) {
    __shared__ float Xs[GBM * XS];
    __shared__ float Bs[EMB];

    int tid  = threadIdx.x;
    int row0 = blockIdx.x * GBM;

    if (tid < EMB) Bs[tid] = 2.0f * b1l[tid] + b2l[tid];

    const float4* E4 = (const float4*)g_E;
    const float4* L4 = (const float4*)g_LEsel;
    for (int j = tid; j < GBM * EMBV; j += GT) {
        int r = j / EMBV, c = j % EMBV;
        int entry = row0 + r;
        int node  = g_nodes[entry];
        float4 le = L4[(size_t)entry * EMBV + c];
        float4 e  = E4[(size_t)node  * EMBV + c];
        float4* xr = (float4*)(Xs + r * XS);
        xr[c]        = make_float4(le.x + e.x, le.y + e.y, le.z + e.z, le.w + e.w);
        xr[EMBV + c] = make_float4(le.x * e.x, le.y * e.y, le.z * e.z, le.w * e.w);
    }
    __syncthreads();

    gemm_core_epilogue(Xs, Bs, tid, W1l, W2l, (float4*)g_Esel, nullptr, row0, NSEL);
}

// ---------------- gather + row-normalize selected rows into output ----------------
__global__ void k_gather(const int* __restrict__ u_id, const int* __restrict__ pos,
                         const int* __restrict__ neg, float* __restrict__ out,
                         int layer, int virt) {
    int gw   = (blockIdx.x * blockDim.x + threadIdx.x) >> 5;
    int lane = threadIdx.x & 31;
    if (gw >= NSEL) return;
    int node;
    if (gw < BATCH_)          node = u_id[gw];
    else if (gw < 2 * BATCH_) node = N_USER + pos[gw - BATCH_];
    else                      node = N_USER + neg[gw - 2 * BATCH_];

    const float4* src = virt ? (const float4*)g_ptr[node]
                             : ((const float4*)g_E) + (size_t)node * EMBV;
    float4 v = make_float4(0.f, 0.f, 0.f, 0.f);
    if (lane < EMBV) v = __ldg(&src[lane]);
    float ss = v.x * v.x + v.y * v.y + v.z * v.z + v.w * v.w;
    #pragma unroll
    for (int o = 16; o; o >>= 1) ss += __shfl_xor_sync(0xffffffffu, ss, o);
    float scale = 1.0f;
    if (layer > 0) scale = 1.0f / fmaxf(sqrtf(ss), 1e-12f);
    if (lane < EMBV) {
        float4 r = make_float4(v.x * scale, v.y * scale, v.z * scale, v.w * scale);
        ((float4*)(out + (size_t)gw * (4 * EMB) + layer * EMB))[lane] = r;
    }
}

__global__ void k_gather_sel(float* __restrict__ out, int layer) {
    int gw   = (blockIdx.x * blockDim.x + threadIdx.x) >> 5;
    int lane = threadIdx.x & 31;
    if (gw >= NSEL) return;
    const float4* E4 = (const float4*)g_Esel;
    float4 v = make_float4(0.f, 0.f, 0.f, 0.f);
    if (lane < EMBV) v = E4[(size_t)gw * EMBV + lane];
    float ss = v.x * v.x + v.y * v.y + v.z * v.z + v.w * v.w;
    #pragma unroll
    for (int o = 16; o; o >>= 1) ss += __shfl_xor_sync(0xffffffffu, ss, o);
    float scale = 1.0f / fmaxf(sqrtf(ss), 1e-12f);
    if (lane < EMBV) {
        float4 r = make_float4(v.x * scale, v.y * scale, v.z * scale, v.w * scale);
        ((float4*)(out + (size_t)gw * (4 * EMB) + layer * EMB))[lane] = r;
    }
}

// ---------------- launch (single stream, proven R12 ordering) ----------------
extern "C" void kernel_launch(void* const* d_in, const int* in_sizes, int n_in,
                              void* d_out, int out_size) {
    const int*   u_id      = (const int*)d_in[0];
    const int*   age       = (const int*)d_in[1];
    const int*   sex       = (const int*)d_in[2];
    const int*   month     = (const int*)d_in[3];
    const int*   day       = (const int*)d_in[4];
    const int*   dow       = (const int*)d_in[5];
    const int*   pos       = (const int*)d_in[6];
    const int*   neg       = (const int*)d_in[7];
    const int*   lrows     = (const int*)d_in[8];
    const int*   lcols     = (const int*)d_in[9];
    const float* lvals     = (const float*)d_in[10];
    const float* user_tab  = (const float*)d_in[11];
    const float* item_tab  = (const float*)d_in[12];
    const float* age_tab   = (const float*)d_in[13];
    const float* sex_tab   = (const float*)d_in[14];
    const float* month_tab = (const float*)d_in[15];
    const float* day_tab   = (const float*)d_in[16];
    const float* dow_tab   = (const float*)d_in[17];
    const float* W1        = (const float*)d_in[18];
    const float* b1        = (const float*)d_in[19];
    const float* W2        = (const float*)d_in[20];
    const float* b2        = (const float*)d_in[21];
    float* out = (float*)d_out;

    const int GMAX = (N_NODES_ + GBM - 1) / GBM;

    // CSR build + virtual-E0 pointer table
    k_init<<<(N_NODES_ + 255) / 256, 256>>>();
    k_init_ptr<<<(N_NODES_ + 255) / 256, 256>>>(user_tab, item_tab);
    k_hist<<<(NNZ_ / 4 + 255) / 256, 256>>>((const int4*)lrows);
    int nb = (N_NODES_ + 1023) / 1024;
    k_scan1<<<nb, 1024>>>();
    k_scan2<<<1, 1024>>>(nb);
    k_scan3<<<(N_NODES_ + 255) / 256, 256>>>();
    k_scatter<<<(NNZ_ / 4 + 255) / 256, 256>>>((const int4*)lrows, (const int4*)lcols,
                                               (const int4*)lvals);

    // blend (writes into g_E, repoints) + node list
    k_winner<<<(BATCH_ + 255) / 256, 256>>>(u_id);
    k_blend<<<(BATCH_ + 255) / 256, 256>>>(u_id, age, sex, month, day, dow, user_tab,
                                           age_tab, sex_tab, month_tab, day_tab, dow_tab);
    k_nodes<<<(NSEL + 255) / 256, 256>>>(u_id, pos, neg);

    // frontier sets: S1 = Ssel ∪ N(Ssel); S2 = S1 ∪ N(S1)
    k_mark_sel<<<(NSEL * 32 + 255) / 256, 256>>>();
    k_compact1<<<(N_NODES_ + 255) / 256, 256>>>();
    k_mark_list<<<1024, 256>>>();
    k_compact2<<<(N_NODES_ + 255) / 256, 256>>>();

    // layer-0 slice (unnormalized E0, via pointer table)
    k_gather<<<(NSEL * 32 + 255) / 256, 256>>>(u_id, pos, neg, out, 0, 1);

    // layer 0 over S2 (virtual E0 reads; writes E1 into g_E)
    k_spmm_l<<<2048, 256>>>(0, 1);
    k_gemm_l<<<GMAX, GT>>>(0, 1, W1, b1, W2, b2);
    k_gather<<<(NSEL * 32 + 255) / 256, 256>>>(u_id, pos, neg, out, 1, 0);

    // layer 1 over S1
    k_spmm_l<<<2048, 256>>>(1, 0);
    k_gemm_l<<<GMAX, GT>>>(1, 0, W1 + (size_t)EMB * EMB, b1 + EMB,
                                 W2 + (size_t)EMB * EMB, b2 + EMB);
    k_gather<<<(NSEL * 32 + 255) / 256, 256>>>(u_id, pos, neg, out, 2, 0);

    // layer 2: selective (entry-indexed)
    k_spmm_sel<<<(NSEL * 32 + 255) / 256, 256>>>();
    k_gemm_sel<<<NSEL / GBM, GT>>>(W1 + (size_t)2 * EMB * EMB, b1 + 2 * EMB,
                                   W2 + (size_t)2 * EMB * EMB, b2 + 2 * EMB);
    k_gather_sel<<<(NSEL * 32 + 255) / 256, 256>>>(out, NLAYER);
}